// round 16
// baseline (speedup 1.0000x reference)
#include <cuda_runtime.h>
#include <cuda_bf16.h>
#include <cstdint>

// Problem dims (fixed)
#define B    32
#define T    64
#define DIN  10000
#define H    200
#define NCLS 2
#define M_TOT (B * T)          // 2048
#define KPAD 10240             // DIN padded to multiple of 64

#define KSPLIT 8
#define KC    (KPAD / KSPLIT)  // 1280
#define KB    64               // k per smem chunk
#define NCHUNK (KC / KB)       // 20

#define NPAD 224               // CTA N tile (200 real + 24 zero pad)
#define SMSTRIDE 72            // bf16 elems per smem row (64 + 8 pad)
#define ROWB (SMSTRIDE * 2)    // 144 bytes

// smem buffer layout (bytes, per stage)
#define OFF_AH 0
#define OFF_AL (128 * ROWB)                 // 18432
#define OFF_WH (2 * 128 * ROWB)             // 36864
#define OFF_WL (2 * 128 * ROWB + NPAD * ROWB)   // 69120
#define BUFB   (2 * 128 * ROWB + 2 * NPAD * ROWB)  // 101376
#define GEMM_SMEM (2 * BUFB)                // 202752

// Scratch (device globals: no allocation allowed)
__device__ float g_pre[M_TOT * H];
__device__ float g_h[M_TOT * H];
__device__ float g_part[KSPLIT * M_TOT * H];
__device__ __nv_bfloat16 g_Whi[(size_t)H * KPAD];
__device__ __nv_bfloat16 g_Wlo[(size_t)H * KPAD];

// ---------------------------------------------------------------------------
// Helpers
// ---------------------------------------------------------------------------
__device__ __forceinline__ void cp16(void* dst, const void* src, int srcsize) {
    uint32_t d = (uint32_t)__cvta_generic_to_shared(dst);
    asm volatile("cp.async.cg.shared.global [%0], [%1], 16, %2;"
                 :: "r"(d), "l"(src), "r"(srcsize) : "memory");
}
__device__ __forceinline__ void cp_commit() {
    asm volatile("cp.async.commit_group;" ::: "memory");
}
template <int N>
__device__ __forceinline__ void cp_wait() {
    asm volatile("cp.async.wait_group %0;" :: "n"(N) : "memory");
}
__device__ __forceinline__ void mma_bf16(float* c, const uint32_t* a,
                                         uint32_t b0, uint32_t b1) {
    asm volatile(
        "mma.sync.aligned.m16n8k16.row.col.f32.bf16.bf16.f32 "
        "{%0,%1,%2,%3}, {%4,%5,%6,%7}, {%8,%9}, {%0,%1,%2,%3};"
        : "+f"(c[0]), "+f"(c[1]), "+f"(c[2]), "+f"(c[3])
        : "r"(a[0]), "r"(a[1]), "r"(a[2]), "r"(a[3]), "r"(b0), "r"(b1));
}
__device__ __forceinline__ uint32_t lds32(const char* base, int row, int col_bf16) {
    return *(const uint32_t*)(base + row * ROWB + col_bf16 * 2);
}
// packed fp32x2 FMA (exact fp32 math)
__device__ __forceinline__ void fma2(unsigned long long& c,
                                     unsigned long long a, unsigned long long b) {
    asm("fma.rn.f32x2 %0, %1, %2, %3;" : "=l"(c) : "l"(a), "l"(b), "l"(c));
}
__device__ __forceinline__ float2 upk(unsigned long long v) {
    uint32_t lo, hi;
    asm("mov.b64 {%0,%1}, %2;" : "=r"(lo), "=r"(hi) : "l"(v));
    return make_float2(__uint_as_float(lo), __uint_as_float(hi));
}
__device__ __forceinline__ unsigned long long pk2(float a, float b) {
    unsigned long long r;
    asm("mov.b64 %0, {%1, %2};" : "=l"(r) : "f"(a), "f"(b));
    return r;
}
// Fast tanh (clamped exp2/rcp form), abs err ~1e-6.
__device__ __forceinline__ float fast_tanh(float x) {
    x = fminf(fmaxf(x, -15.0f), 15.0f);
    float e;
    asm("ex2.approx.f32 %0, %1;" : "=f"(e) : "f"(x * 2.885390081777926f));
    float d = e + 1.0f;
    float r;
    asm("rcp.approx.f32 %0, %1;" : "=f"(r) : "f"(d));
    r = r * (2.0f - d * r);
    return 1.0f - 2.0f * r;
}

// ---------------------------------------------------------------------------
// Split-convert fp32 -> (hi, lo) bf16, zero-padded K -> KPAD (W only).
// ---------------------------------------------------------------------------
__global__ void cvt_split4(const float* __restrict__ src,
                           __nv_bfloat16* __restrict__ hi,
                           __nv_bfloat16* __restrict__ lo,
                           int rows, int K) {
    int i = blockIdx.x * blockDim.x + threadIdx.x;
    int per_row = KPAD / 4;
    if (i >= rows * per_row) return;
    int r = i / per_row;
    int k4 = (i % per_row) * 4;

    float4 v = make_float4(0.f, 0.f, 0.f, 0.f);
    if (k4 < K) v = *(const float4*)&src[(size_t)r * K + k4];   // K % 4 == 0

    __nv_bfloat16 h[4], l[4];
    float vv[4] = {v.x, v.y, v.z, v.w};
    #pragma unroll
    for (int j = 0; j < 4; j++) {
        h[j] = __float2bfloat16(vv[j]);
        l[j] = __float2bfloat16(vv[j] - __bfloat162float(h[j]));
    }
    size_t o = (size_t)r * KPAD + k4;
    *(uint2*)&hi[o] = *(uint2*)h;
    *(uint2*)&lo[o] = *(uint2*)l;
}

// ---------------------------------------------------------------------------
// Layer-0 GEMM on HMMA, fused fp32->bf16-split A conversion.
// 256 threads / 8 warps, warp tile m64 x n56 (4 m-subtiles): W-fragment
// reuse doubles, per-warp ILP doubles; reg budget ~190 legal at 256 thr.
// Same M-tile 128 / KB 64 / smem layout as the measured-best R12 shape.
// ---------------------------------------------------------------------------
__global__ __launch_bounds__(256, 1)
void gemm0_mma(const float* __restrict__ x,
               const __nv_bfloat16* __restrict__ Whi,
               const __nv_bfloat16* __restrict__ Wlo,
               float* __restrict__ part) {
    extern __shared__ char sm[];

    const int tid  = threadIdx.x;
    const int wid  = tid >> 5;
    const int lane = tid & 31;
    const int grp  = lane >> 2;        // 0..7
    const int tig  = lane & 3;         // 0..3
    const int wm   = wid & 1;          // m warp 0..1 (64 rows each)
    const int wn   = wid >> 1;         // n warp 0..3 (56 cols each)

    const int kz   = blockIdx.x;
    const int bm   = blockIdx.y * 128;
    const int kbeg = kz * KC;

    const float* Am = x + (size_t)bm * DIN;

    // A loader: 2048 float4 slots over 256 threads -> 8 per thread.
    // slot = tid + u*256; row = slot>>4 (0..127), col = (slot&15)*4.
    float4 areg[8];
    auto ldgA = [&](int k0) {
        #pragma unroll
        for (int u = 0; u < 8; u++) {
            int slot = tid + u * 256;
            int row = slot >> 4;
            int k = k0 + (slot & 15) * 4;
            if (k + 4 <= DIN)
                areg[u] = *(const float4*)&Am[(size_t)row * DIN + k];
            else
                areg[u] = make_float4(0.f, 0.f, 0.f, 0.f);
        }
    };
    auto stsA = [&](char* buf) {
        #pragma unroll
        for (int u = 0; u < 8; u++) {
            int slot = tid + u * 256;
            int row = slot >> 4;
            int off = row * ROWB + (slot & 15) * 8;   // 4 bf16 = 8 bytes
            float v[4] = {areg[u].x, areg[u].y, areg[u].z, areg[u].w};
            __nv_bfloat16 h4[4], l4[4];
            #pragma unroll
            for (int j = 0; j < 4; j++) {
                h4[j] = __float2bfloat16(v[j]);
                l4[j] = __float2bfloat16(v[j] - __bfloat162float(h4[j]));
            }
            *(uint2*)(buf + OFF_AH + off) = *(uint2*)h4;
            *(uint2*)(buf + OFF_AL + off) = *(uint2*)l4;
        }
    };
    auto ldW = [&](char* buf, int k0) {
        #pragma unroll
        for (int i = tid; i < NPAD * 8; i += 256) {
            int r = i >> 3, q = i & 7;
            int off = r * ROWB + q * 16;
            int rr = r < H ? r : H - 1;
            int sz = r < H ? 16 : 0;
            size_t go = (size_t)rr * KPAD + k0 + q * 8;
            cp16(buf + OFF_WH + off, Whi + go, sz);
            cp16(buf + OFF_WL + off, Wlo + go, sz);
        }
    };

    float acc[4][7][4] = {};

    // prologue: chunk 0
    ldgA(kbeg);
    ldW(sm, kbeg);
    cp_commit();
    stsA(sm);
    cp_wait<0>();
    __syncthreads();

    for (int c = 0; c < NCHUNK; c++) {
        char* buf = sm + (c & 1) * BUFB;
        char* nbuf = sm + ((c + 1) & 1) * BUFB;

        if (c + 1 < NCHUNK) {
            ldgA(kbeg + (c + 1) * KB);
            ldW(nbuf, kbeg + (c + 1) * KB);
            cp_commit();
        }

        const char* Ah = buf + OFF_AH;
        const char* Al = buf + OFF_AL;
        const char* Wh = buf + OFF_WH;
        const char* Wl = buf + OFF_WL;

        #pragma unroll
        for (int ks = 0; ks < 4; ks++) {
            const int kc = ks * 16 + tig * 2;
            uint32_t ah[4][4], al[4][4];
            #pragma unroll
            for (int mt = 0; mt < 4; mt++) {
                int r = wm * 64 + mt * 16 + grp;
                ah[mt][0] = lds32(Ah, r,     kc);
                ah[mt][1] = lds32(Ah, r + 8, kc);
                ah[mt][2] = lds32(Ah, r,     kc + 8);
                ah[mt][3] = lds32(Ah, r + 8, kc + 8);
                al[mt][0] = lds32(Al, r,     kc);
                al[mt][1] = lds32(Al, r + 8, kc);
                al[mt][2] = lds32(Al, r,     kc + 8);
                al[mt][3] = lds32(Al, r + 8, kc + 8);
            }
            #pragma unroll
            for (int j = 0; j < 7; j++) {
                int n = wn * 56 + j * 8 + grp;
                uint32_t bh0 = lds32(Wh, n, kc);
                uint32_t bh1 = lds32(Wh, n, kc + 8);
                uint32_t bl0 = lds32(Wl, n, kc);
                uint32_t bl1 = lds32(Wl, n, kc + 8);
                #pragma unroll
                for (int mt = 0; mt < 4; mt++) {
                    mma_bf16(acc[mt][j], ah[mt], bh0, bh1);   // Ahi*Whi
                    mma_bf16(acc[mt][j], al[mt], bh0, bh1);   // Alo*Whi
                    mma_bf16(acc[mt][j], ah[mt], bl0, bl1);   // Ahi*Wlo
                }
            }
        }

        if (c + 1 < NCHUNK) {
            stsA(nbuf);
            cp_wait<0>();
        }
        __syncthreads();
    }

    // epilogue: write fp32 partials
    float* pz = part + (size_t)kz * M_TOT * H;
    #pragma unroll
    for (int mt = 0; mt < 4; mt++) {
        #pragma unroll
        for (int j = 0; j < 7; j++) {
            int n = wn * 56 + j * 8 + tig * 2;
            if (n >= H) continue;
            int m0 = bm + wm * 64 + mt * 16 + grp;
            *(float2*)&pz[(size_t)m0 * H + n]       = make_float2(acc[mt][j][0], acc[mt][j][1]);
            *(float2*)&pz[(size_t)(m0 + 8) * H + n] = make_float2(acc[mt][j][2], acc[mt][j][3]);
        }
    }
}

// Sum K-split partials + both biases -> pre (bandwidth-bound, wide grid)
__global__ void reduce_bias(const float* __restrict__ part,
                            const float* __restrict__ b1,
                            const float* __restrict__ b2,
                            float* __restrict__ pre) {
    int i = blockIdx.x * blockDim.x + threadIdx.x;
    if (i >= M_TOT * H) return;
    const int MH = M_TOT * H;
    int n = i % H;
    float s = b1[n] + b2[n];
    #pragma unroll
    for (int z = 0; z < KSPLIT; z++) s += part[i + (size_t)z * MH];
    pre[i] = s;
}

// ---------------------------------------------------------------------------
// GEMM for K=200 layers (confirmed 14.2us): whole-K in smem, 256 threads,
// 4x4 micro-tile, one barrier, fma.rn.f32x2.
// ---------------------------------------------------------------------------
#define SG_ASTRIDE 212
#define SG_SMEM ((64 * SG_ASTRIDE + 200 * 64) * 4)   // 105472 B

__global__ __launch_bounds__(256, 1)
void gemm_abt_bias(const float* __restrict__ A,
                   const float* __restrict__ W,
                   const float* __restrict__ b1,
                   const float* __restrict__ b2,
                   float* __restrict__ C) {
    extern __shared__ float s[];
    float* As = s;                     // [64][212]
    float* Ws = s + 64 * SG_ASTRIDE;   // [200][64] k-major

    const int bm = blockIdx.y * 64;
    const int bn = blockIdx.x * 64;
    const int tid = threadIdx.x;
    const int tx = tid % 16;
    const int ty = tid / 16;
    const int lm = tid >> 2;       // 0..63
    const int lq = tid & 3;

    #pragma unroll
    for (int q = lq; q < 50; q += 4) {
        float4 v = *(const float4*)&A[(size_t)(bm + lm) * H + q * 4];
        *(float4*)&As[lm * SG_ASTRIDE + q * 4] = v;
    }
    {
        int n = bn + lm;
        #pragma unroll
        for (int q = lq; q < 50; q += 4) {
            float4 v = make_float4(0.f, 0.f, 0.f, 0.f);
            if (n < H) v = *(const float4*)&W[(size_t)n * H + q * 4];
            Ws[(q * 4 + 0) * 64 + lm] = v.x;
            Ws[(q * 4 + 1) * 64 + lm] = v.y;
            Ws[(q * 4 + 2) * 64 + lm] = v.z;
            Ws[(q * 4 + 3) * 64 + lm] = v.w;
        }
    }
    __syncthreads();

    unsigned long long acc2[4][2] = {};

    #pragma unroll 8
    for (int kk = 0; kk < H; kk++) {
        ulonglong2 wp = *(const ulonglong2*)&Ws[kk * 64 + tx * 4];
        #pragma unroll
        for (int i = 0; i < 4; i++) {
            float a = As[(ty * 4 + i) * SG_ASTRIDE + kk];
            unsigned long long aa = pk2(a, a);
            fma2(acc2[i][0], aa, wp.x);
            fma2(acc2[i][1], aa, wp.y);
        }
    }

    #pragma unroll
    for (int i = 0; i < 4; i++) {
        int m = bm + ty * 4 + i;
        #pragma unroll
        for (int jj = 0; jj < 2; jj++) {
            float2 p = upk(acc2[i][jj]);
            int n0 = bn + tx * 4 + jj * 2;
            if (n0 < H)     C[(size_t)m * H + n0]     = p.x + b1[n0] + b2[n0];
            if (n0 + 1 < H) C[(size_t)m * H + n0 + 1] = p.y + b1[n0 + 1] + b2[n0 + 1];
        }
    }
}

// ---------------------------------------------------------------------------
// Recurrent scan: one CTA per batch row, 400 threads = 2 k-splits x 200
// outputs (best measured). Optional fused FC epilogue for the last layer.
// ---------------------------------------------------------------------------
#define SCAN_THREADS 400
#define SCAN_SMEM (T * H * 4)

__global__ __launch_bounds__(SCAN_THREADS, 1)
void rnn_scan(const float* __restrict__ pre,
              const float* __restrict__ W_hh,
              float* __restrict__ hseq,
              const float* __restrict__ fc_w,
              const float* __restrict__ fc_b,
              float* __restrict__ out,
              int do_fc) {
    extern __shared__ float pres[];                 // [T*H]; becomes h history
    __shared__ __align__(16) float hbuf[2][200];
    __shared__ float partial[2][200];

    const int b = blockIdx.x;
    const int tid = threadIdx.x;
    const int n = tid % H;
    const int q = tid / H;       // 0 or 1

    ulonglong2 wr[25];
    #pragma unroll
    for (int j = 0; j < 25; j++) {
        int k = q * 4 + 8 * j;
        wr[j] = *(const ulonglong2*)&W_hh[(size_t)n * H + k];
    }

    const float* preb = pre + (size_t)b * T * H;
    for (int i = tid; i < T * H; i += SCAN_THREADS) pres[i] = preb[i];
    if (tid < 200) { hbuf[0][tid] = 0.f; hbuf[1][tid] = 0.f; }
    __syncthreads();

    int cur = 0;
    for (int t = 0; t < T; t++) {
        unsigned long long a0 = 0ull, a1 = 0ull;
        #pragma unroll
        for (int j = 0; j < 25; j++) {
            int k = q * 4 + 8 * j;
            ulonglong2 h2 = *(const ulonglong2*)&hbuf[cur][k];
            fma2(a0, wr[j].x, h2.x);
            fma2(a1, wr[j].y, h2.y);
        }
        float2 p0 = upk(a0), p1 = upk(a1);
        partial[q][n] = (p0.x + p0.y) + (p1.x + p1.y);
        __syncthreads();

        if (tid < H) {
            float v = fast_tanh(pres[t * H + tid]
                                + partial[0][tid] + partial[1][tid]);
            hbuf[cur ^ 1][tid] = v;
            pres[t * H + tid] = v;
        }
        __syncthreads();
        cur ^= 1;
    }

    if (do_fc) {
        if (tid < 64) {
            int c = tid >> 5;
            int lane = tid & 31;
            const float* hl = &pres[(T - 1) * H];
            const float* w = fc_w + c * H;
            float acc = 0.f;
            for (int k = lane; k < H; k += 32) acc += hl[k] * w[k];
            #pragma unroll
            for (int o = 16; o > 0; o >>= 1)
                acc += __shfl_xor_sync(0xffffffffu, acc, o);
            if (lane == 0) out[b * NCLS + c] = acc + fc_b[c];
        }
    } else {
        float4* outb = (float4*)(hseq + (size_t)b * T * H);
        const float4* src = (const float4*)pres;
        for (int i = tid; i < (T * H) / 4; i += SCAN_THREADS) outb[i] = src[i];
    }
}

// ---------------------------------------------------------------------------
// Launch
// ---------------------------------------------------------------------------
extern "C" void kernel_launch(void* const* d_in, const int* in_sizes, int n_in,
                              void* d_out, int out_size) {
    const float* x     = (const float*)d_in[0];
    const float* W_ih0 = (const float*)d_in[1];
    const float* W_hh0 = (const float*)d_in[2];
    const float* b_ih0 = (const float*)d_in[3];
    const float* b_hh0 = (const float*)d_in[4];
    const float* W_ih1 = (const float*)d_in[5];
    const float* W_hh1 = (const float*)d_in[6];
    const float* b_ih1 = (const float*)d_in[7];
    const float* b_hh1 = (const float*)d_in[8];
    const float* W_ih2 = (const float*)d_in[9];
    const float* W_hh2 = (const float*)d_in[10];
    const float* b_ih2 = (const float*)d_in[11];
    const float* b_hh2 = (const float*)d_in[12];
    const float* fc_w  = (const float*)d_in[13];
    const float* fc_b  = (const float*)d_in[14];

    float *pre, *h, *part;
    __nv_bfloat16 *Whi, *Wlo;
    cudaGetSymbolAddress((void**)&pre,  g_pre);
    cudaGetSymbolAddress((void**)&h,    g_h);
    cudaGetSymbolAddress((void**)&part, g_part);
    cudaGetSymbolAddress((void**)&Whi,  g_Whi);
    cudaGetSymbolAddress((void**)&Wlo,  g_Wlo);

    cudaFuncSetAttribute(rnn_scan, cudaFuncAttributeMaxDynamicSharedMemorySize, SCAN_SMEM);
    cudaFuncSetAttribute(gemm0_mma, cudaFuncAttributeMaxDynamicSharedMemorySize, GEMM_SMEM);
    cudaFuncSetAttribute(gemm_abt_bias, cudaFuncAttributeMaxDynamicSharedMemorySize, SG_SMEM);

    // Layer 0: single W split-convert, HMMA GEMM (K-split), reduce, scan
    cvt_split4<<<(H * (KPAD / 4) + 255) / 256, 256>>>(W_ih0, Whi, Wlo, H, DIN);
    gemm0_mma<<<dim3(KSPLIT, M_TOT / 128), 256, GEMM_SMEM>>>(x, Whi, Wlo, part);
    reduce_bias<<<(M_TOT * H + 255) / 256, 256>>>(part, b_ih0, b_hh0, pre);
    rnn_scan<<<B, SCAN_THREADS, SCAN_SMEM>>>(pre, W_hh0, h, fc_w, fc_b, (float*)d_out, 0);

    dim3 gg((H + 63) / 64, M_TOT / 64);   // (4, 32)

    // Layer 1
    gemm_abt_bias<<<gg, 256, SG_SMEM>>>(h, W_ih1, b_ih1, b_hh1, pre);
    rnn_scan<<<B, SCAN_THREADS, SCAN_SMEM>>>(pre, W_hh1, h, fc_w, fc_b, (float*)d_out, 0);

    // Layer 2 (scan fuses the final FC)
    gemm_abt_bias<<<gg, 256, SG_SMEM>>>(h, W_ih2, b_ih2, b_hh2, pre);
    rnn_scan<<<B, SCAN_THREADS, SCAN_SMEM>>>(pre, W_hh2, h, fc_w, fc_b, (float*)d_out, 1);
}

// round 17
// speedup vs baseline: 1.0083x; 1.0083x over previous
#include <cuda_runtime.h>
#include <cuda_bf16.h>
#include <cstdint>

// Problem dims (fixed)
#define B    32
#define T    64
#define DIN  10000
#define H    200
#define NCLS 2
#define M_TOT (B * T)          // 2048
#define KPAD 10240             // DIN padded to multiple of 64

#define KSPLIT 8
#define KC    (KPAD / KSPLIT)  // 1280
#define KB    64               // k per smem chunk
#define NCHUNK (KC / KB)       // 20

#define NPAD 224               // CTA N tile (200 real + 24 zero pad)
#define SMSTRIDE 72            // bf16 elems per smem row (64 + 8 pad)
#define ROWB (SMSTRIDE * 2)    // 144 bytes

// smem buffer layout (bytes, per stage)
#define OFF_AH 0
#define OFF_AL (128 * ROWB)                 // 18432
#define OFF_WH (2 * 128 * ROWB)             // 36864
#define OFF_WL (2 * 128 * ROWB + NPAD * ROWB)   // 69120
#define BUFB   (2 * 128 * ROWB + 2 * NPAD * ROWB)  // 101376
#define GEMM_SMEM (2 * BUFB)                // 202752

// Scratch (device globals: no allocation allowed)
__device__ float g_pre[M_TOT * H];
__device__ float g_h[M_TOT * H];
__device__ float g_part[KSPLIT * M_TOT * H];
__device__ __nv_bfloat16 g_Whi[(size_t)H * KPAD];
__device__ __nv_bfloat16 g_Wlo[(size_t)H * KPAD];

// ---------------------------------------------------------------------------
// Helpers
// ---------------------------------------------------------------------------
__device__ __forceinline__ void cp16(void* dst, const void* src, int srcsize) {
    uint32_t d = (uint32_t)__cvta_generic_to_shared(dst);
    asm volatile("cp.async.cg.shared.global [%0], [%1], 16, %2;"
                 :: "r"(d), "l"(src), "r"(srcsize) : "memory");
}
__device__ __forceinline__ void cp_commit() {
    asm volatile("cp.async.commit_group;" ::: "memory");
}
template <int N>
__device__ __forceinline__ void cp_wait() {
    asm volatile("cp.async.wait_group %0;" :: "n"(N) : "memory");
}
__device__ __forceinline__ void mma_bf16(float* c, const uint32_t* a,
                                         uint32_t b0, uint32_t b1) {
    asm volatile(
        "mma.sync.aligned.m16n8k16.row.col.f32.bf16.bf16.f32 "
        "{%0,%1,%2,%3}, {%4,%5,%6,%7}, {%8,%9}, {%0,%1,%2,%3};"
        : "+f"(c[0]), "+f"(c[1]), "+f"(c[2]), "+f"(c[3])
        : "r"(a[0]), "r"(a[1]), "r"(a[2]), "r"(a[3]), "r"(b0), "r"(b1));
}
__device__ __forceinline__ uint32_t lds32(const char* base, int row, int col_bf16) {
    return *(const uint32_t*)(base + row * ROWB + col_bf16 * 2);
}
// packed fp32x2 FMA (exact fp32 math)
__device__ __forceinline__ void fma2(unsigned long long& c,
                                     unsigned long long a, unsigned long long b) {
    asm("fma.rn.f32x2 %0, %1, %2, %3;" : "=l"(c) : "l"(a), "l"(b), "l"(c));
}
__device__ __forceinline__ float2 upk(unsigned long long v) {
    uint32_t lo, hi;
    asm("mov.b64 {%0,%1}, %2;" : "=r"(lo), "=r"(hi) : "l"(v));
    return make_float2(__uint_as_float(lo), __uint_as_float(hi));
}
__device__ __forceinline__ unsigned long long pk2(float a, float b) {
    unsigned long long r;
    asm("mov.b64 %0, {%1, %2};" : "=l"(r) : "f"(a), "f"(b));
    return r;
}
// Fast tanh (clamped exp2/rcp form), abs err ~1e-6.
__device__ __forceinline__ float fast_tanh(float x) {
    x = fminf(fmaxf(x, -15.0f), 15.0f);
    float e;
    asm("ex2.approx.f32 %0, %1;" : "=f"(e) : "f"(x * 2.885390081777926f));
    float d = e + 1.0f;
    float r;
    asm("rcp.approx.f32 %0, %1;" : "=f"(r) : "f"(d));
    r = r * (2.0f - d * r);
    return 1.0f - 2.0f * r;
}

// ---------------------------------------------------------------------------
// Split-convert fp32 -> (hi, lo) bf16, zero-padded K -> KPAD (W only).
// ---------------------------------------------------------------------------
__global__ void cvt_split4(const float* __restrict__ src,
                           __nv_bfloat16* __restrict__ hi,
                           __nv_bfloat16* __restrict__ lo,
                           int rows, int K) {
    int i = blockIdx.x * blockDim.x + threadIdx.x;
    int per_row = KPAD / 4;
    if (i >= rows * per_row) return;
    int r = i / per_row;
    int k4 = (i % per_row) * 4;

    float4 v = make_float4(0.f, 0.f, 0.f, 0.f);
    if (k4 < K) v = *(const float4*)&src[(size_t)r * K + k4];   // K % 4 == 0

    __nv_bfloat16 h[4], l[4];
    float vv[4] = {v.x, v.y, v.z, v.w};
    #pragma unroll
    for (int j = 0; j < 4; j++) {
        h[j] = __float2bfloat16(vv[j]);
        l[j] = __float2bfloat16(vv[j] - __bfloat162float(h[j]));
    }
    size_t o = (size_t)r * KPAD + k4;
    *(uint2*)&hi[o] = *(uint2*)h;
    *(uint2*)&lo[o] = *(uint2*)l;
}

// ---------------------------------------------------------------------------
// Layer-0 GEMM on HMMA with fused fp32->bf16-split A conversion.
// (R12/R15 proven shape: 512 thr, M-tile 128, KB=64, interleaved inner loop)
// ---------------------------------------------------------------------------
__global__ __launch_bounds__(512, 1)
void gemm0_mma(const float* __restrict__ x,
               const __nv_bfloat16* __restrict__ Whi,
               const __nv_bfloat16* __restrict__ Wlo,
               float* __restrict__ part) {
    extern __shared__ char sm[];

    const int tid  = threadIdx.x;
    const int wid  = tid >> 5;
    const int lane = tid & 31;
    const int grp  = lane >> 2;        // 0..7
    const int tig  = lane & 3;         // 0..3
    const int wm   = wid & 3;          // m warp 0..3
    const int wn   = wid >> 2;         // n warp 0..3

    const int kz   = blockIdx.x;
    const int bm   = blockIdx.y * 128;
    const int kbeg = kz * KC;

    const float* Am = x + (size_t)bm * DIN;

    const int ar   = tid >> 2;          // 0..127
    const int asub = (tid & 3) * 4;     // 0,4,8,12

    float4 areg[4];
    auto ldgA = [&](int k0) {
        #pragma unroll
        for (int u = 0; u < 4; u++) {
            int k = k0 + asub + 16 * u;
            if (k + 4 <= DIN)
                areg[u] = *(const float4*)&Am[(size_t)ar * DIN + k];
            else
                areg[u] = make_float4(0.f, 0.f, 0.f, 0.f);
        }
    };
    auto stsA = [&](char* buf) {
        #pragma unroll
        for (int u = 0; u < 4; u++) {
            int koff = asub + 16 * u;
            float v[4] = {areg[u].x, areg[u].y, areg[u].z, areg[u].w};
            __nv_bfloat16 h4[4], l4[4];
            #pragma unroll
            for (int j = 0; j < 4; j++) {
                h4[j] = __float2bfloat16(v[j]);
                l4[j] = __float2bfloat16(v[j] - __bfloat162float(h4[j]));
            }
            *(uint2*)(buf + OFF_AH + ar * ROWB + koff * 2) = *(uint2*)h4;
            *(uint2*)(buf + OFF_AL + ar * ROWB + koff * 2) = *(uint2*)l4;
        }
    };
    auto ldW = [&](char* buf, int k0) {
        #pragma unroll
        for (int i = tid; i < NPAD * 8; i += 512) {
            int r = i >> 3, q = i & 7;
            int off = r * ROWB + q * 16;
            int rr = r < H ? r : H - 1;
            int sz = r < H ? 16 : 0;
            size_t go = (size_t)rr * KPAD + k0 + q * 8;
            cp16(buf + OFF_WH + off, Whi + go, sz);
            cp16(buf + OFF_WL + off, Wlo + go, sz);
        }
    };

    float acc[2][7][4] = {};

    // prologue: chunk 0
    ldgA(kbeg);
    ldW(sm, kbeg);
    cp_commit();
    stsA(sm);
    cp_wait<0>();
    __syncthreads();

    for (int c = 0; c < NCHUNK; c++) {
        char* buf = sm + (c & 1) * BUFB;
        char* nbuf = sm + ((c + 1) & 1) * BUFB;

        if (c + 1 < NCHUNK) {
            ldgA(kbeg + (c + 1) * KB);
            ldW(nbuf, kbeg + (c + 1) * KB);
            cp_commit();
        }

        const char* Ah = buf + OFF_AH;
        const char* Al = buf + OFF_AL;
        const char* Wh = buf + OFF_WH;
        const char* Wl = buf + OFF_WL;

        #pragma unroll
        for (int ks = 0; ks < 4; ks++) {
            const int kc = ks * 16 + tig * 2;
            uint32_t ah[2][4], al[2][4];
            #pragma unroll
            for (int mt = 0; mt < 2; mt++) {
                int r = wm * 32 + mt * 16 + grp;
                ah[mt][0] = lds32(Ah, r,     kc);
                ah[mt][1] = lds32(Ah, r + 8, kc);
                ah[mt][2] = lds32(Ah, r,     kc + 8);
                ah[mt][3] = lds32(Ah, r + 8, kc + 8);
                al[mt][0] = lds32(Al, r,     kc);
                al[mt][1] = lds32(Al, r + 8, kc);
                al[mt][2] = lds32(Al, r,     kc + 8);
                al[mt][3] = lds32(Al, r + 8, kc + 8);
            }
            #pragma unroll
            for (int j = 0; j < 7; j++) {
                int n = wn * 56 + j * 8 + grp;
                uint32_t bh0 = lds32(Wh, n, kc);
                uint32_t bh1 = lds32(Wh, n, kc + 8);
                uint32_t bl0 = lds32(Wl, n, kc);
                uint32_t bl1 = lds32(Wl, n, kc + 8);
                mma_bf16(acc[0][j], ah[0], bh0, bh1);   // Ahi*Whi
                mma_bf16(acc[1][j], ah[1], bh0, bh1);
                mma_bf16(acc[0][j], al[0], bh0, bh1);   // Alo*Whi
                mma_bf16(acc[1][j], al[1], bh0, bh1);
                mma_bf16(acc[0][j], ah[0], bl0, bl1);   // Ahi*Wlo
                mma_bf16(acc[1][j], ah[1], bl0, bl1);
            }
        }

        if (c + 1 < NCHUNK) {
            stsA(nbuf);
            cp_wait<0>();
        }
        __syncthreads();
    }

    // epilogue: write fp32 partials
    float* pz = part + (size_t)kz * M_TOT * H;
    #pragma unroll
    for (int mt = 0; mt < 2; mt++) {
        #pragma unroll
        for (int j = 0; j < 7; j++) {
            int n = wn * 56 + j * 8 + tig * 2;
            if (n >= H) continue;
            int m0 = bm + wm * 32 + mt * 16 + grp;
            *(float2*)&pz[(size_t)m0 * H + n]       = make_float2(acc[mt][j][0], acc[mt][j][1]);
            *(float2*)&pz[(size_t)(m0 + 8) * H + n] = make_float2(acc[mt][j][2], acc[mt][j][3]);
        }
    }
}

// Sum K-split partials + both biases -> pre (bandwidth-bound, wide grid)
__global__ void reduce_bias(const float* __restrict__ part,
                            const float* __restrict__ b1,
                            const float* __restrict__ b2,
                            float* __restrict__ pre) {
    int i = blockIdx.x * blockDim.x + threadIdx.x;
    if (i >= M_TOT * H) return;
    const int MH = M_TOT * H;
    int n = i % H;
    float s = b1[n] + b2[n];
    #pragma unroll
    for (int z = 0; z < KSPLIT; z++) s += part[i + (size_t)z * MH];
    pre[i] = s;
}

// ---------------------------------------------------------------------------
// GEMM for K=200 layers (confirmed 14.2us): whole-K in smem, 256 threads,
// 4x4 micro-tile, one barrier, fma.rn.f32x2.
// ---------------------------------------------------------------------------
#define SG_ASTRIDE 212
#define SG_SMEM ((64 * SG_ASTRIDE + 200 * 64) * 4)   // 105472 B

__global__ __launch_bounds__(256, 1)
void gemm_abt_bias(const float* __restrict__ A,
                   const float* __restrict__ W,
                   const float* __restrict__ b1,
                   const float* __restrict__ b2,
                   float* __restrict__ C) {
    extern __shared__ float s[];
    float* As = s;                     // [64][212]
    float* Ws = s + 64 * SG_ASTRIDE;   // [200][64] k-major

    const int bm = blockIdx.y * 64;
    const int bn = blockIdx.x * 64;
    const int tid = threadIdx.x;
    const int tx = tid % 16;
    const int ty = tid / 16;
    const int lm = tid >> 2;       // 0..63
    const int lq = tid & 3;

    #pragma unroll
    for (int q = lq; q < 50; q += 4) {
        float4 v = *(const float4*)&A[(size_t)(bm + lm) * H + q * 4];
        *(float4*)&As[lm * SG_ASTRIDE + q * 4] = v;
    }
    {
        int n = bn + lm;
        #pragma unroll
        for (int q = lq; q < 50; q += 4) {
            float4 v = make_float4(0.f, 0.f, 0.f, 0.f);
            if (n < H) v = *(const float4*)&W[(size_t)n * H + q * 4];
            Ws[(q * 4 + 0) * 64 + lm] = v.x;
            Ws[(q * 4 + 1) * 64 + lm] = v.y;
            Ws[(q * 4 + 2) * 64 + lm] = v.z;
            Ws[(q * 4 + 3) * 64 + lm] = v.w;
        }
    }
    __syncthreads();

    unsigned long long acc2[4][2] = {};

    #pragma unroll 8
    for (int kk = 0; kk < H; kk++) {
        ulonglong2 wp = *(const ulonglong2*)&Ws[kk * 64 + tx * 4];
        #pragma unroll
        for (int i = 0; i < 4; i++) {
            float a = As[(ty * 4 + i) * SG_ASTRIDE + kk];
            unsigned long long aa = pk2(a, a);
            fma2(acc2[i][0], aa, wp.x);
            fma2(acc2[i][1], aa, wp.y);
        }
    }

    #pragma unroll
    for (int i = 0; i < 4; i++) {
        int m = bm + ty * 4 + i;
        #pragma unroll
        for (int jj = 0; jj < 2; jj++) {
            float2 p = upk(acc2[i][jj]);
            int n0 = bn + tx * 4 + jj * 2;
            if (n0 < H)     C[(size_t)m * H + n0]     = p.x + b1[n0] + b2[n0];
            if (n0 + 1 < H) C[(size_t)m * H + n0 + 1] = p.y + b1[n0 + 1] + b2[n0 + 1];
        }
    }
}

// ---------------------------------------------------------------------------
// Recurrent scan: one CTA per batch row, 400 threads = 2 k-splits x 200
// outputs. pres[t] value is PREFETCHED into a register during the dot phase
// (no dependence on partial) so the inter-barrier tanh path is shorter.
// Optional fused FC epilogue for the last layer.
// ---------------------------------------------------------------------------
#define SCAN_THREADS 400
#define SCAN_SMEM (T * H * 4)

__global__ __launch_bounds__(SCAN_THREADS, 1)
void rnn_scan(const float* __restrict__ pre,
              const float* __restrict__ W_hh,
              float* __restrict__ hseq,
              const float* __restrict__ fc_w,
              const float* __restrict__ fc_b,
              float* __restrict__ out,
              int do_fc) {
    extern __shared__ float pres[];                 // [T*H]; becomes h history
    __shared__ __align__(16) float hbuf[2][200];
    __shared__ float partial[2][200];

    const int b = blockIdx.x;
    const int tid = threadIdx.x;
    const int n = tid % H;
    const int q = tid / H;       // 0 or 1

    ulonglong2 wr[25];
    #pragma unroll
    for (int j = 0; j < 25; j++) {
        int k = q * 4 + 8 * j;
        wr[j] = *(const ulonglong2*)&W_hh[(size_t)n * H + k];
    }

    const float* preb = pre + (size_t)b * T * H;
    for (int i = tid; i < T * H; i += SCAN_THREADS) pres[i] = preb[i];
    if (tid < 200) { hbuf[0][tid] = 0.f; hbuf[1][tid] = 0.f; }
    __syncthreads();

    int cur = 0;
    int tbase = 0;                                   // t * H
    for (int t = 0; t < T; t++, tbase += H) {
        // prefetch this step's pre value early (tanh-phase consumers only);
        // pres[tbase+n] is not overwritten until THIS step's tanh phase.
        float pv = 0.f;
        if (q == 0) pv = pres[tbase + n];

        unsigned long long a0 = 0ull, a1 = 0ull;
        #pragma unroll
        for (int j = 0; j < 25; j++) {
            int k = q * 4 + 8 * j;
            ulonglong2 h2 = *(const ulonglong2*)&hbuf[cur][k];
            fma2(a0, wr[j].x, h2.x);
            fma2(a1, wr[j].y, h2.y);
        }
        float2 p0 = upk(a0), p1 = upk(a1);
        partial[q][n] = (p0.x + p0.y) + (p1.x + p1.y);
        __syncthreads();

        if (tid < H) {
            float v = fast_tanh(pv + partial[0][tid] + partial[1][tid]);
            hbuf[cur ^ 1][tid] = v;
            pres[tbase + tid] = v;
        }
        __syncthreads();
        cur ^= 1;
    }

    if (do_fc) {
        if (tid < 64) {
            int c = tid >> 5;
            int lane = tid & 31;
            const float* hl = &pres[(T - 1) * H];
            const float* w = fc_w + c * H;
            float acc = 0.f;
            for (int k = lane; k < H; k += 32) acc += hl[k] * w[k];
            #pragma unroll
            for (int o = 16; o > 0; o >>= 1)
                acc += __shfl_xor_sync(0xffffffffu, acc, o);
            if (lane == 0) out[b * NCLS + c] = acc + fc_b[c];
        }
    } else {
        float4* outb = (float4*)(hseq + (size_t)b * T * H);
        const float4* src = (const float4*)pres;
        for (int i = tid; i < (T * H) / 4; i += SCAN_THREADS) outb[i] = src[i];
    }
}

// ---------------------------------------------------------------------------
// Launch
// ---------------------------------------------------------------------------
extern "C" void kernel_launch(void* const* d_in, const int* in_sizes, int n_in,
                              void* d_out, int out_size) {
    const float* x     = (const float*)d_in[0];
    const float* W_ih0 = (const float*)d_in[1];
    const float* W_hh0 = (const float*)d_in[2];
    const float* b_ih0 = (const float*)d_in[3];
    const float* b_hh0 = (const float*)d_in[4];
    const float* W_ih1 = (const float*)d_in[5];
    const float* W_hh1 = (const float*)d_in[6];
    const float* b_ih1 = (const float*)d_in[7];
    const float* b_hh1 = (const float*)d_in[8];
    const float* W_ih2 = (const float*)d_in[9];
    const float* W_hh2 = (const float*)d_in[10];
    const float* b_ih2 = (const float*)d_in[11];
    const float* b_hh2 = (const float*)d_in[12];
    const float* fc_w  = (const float*)d_in[13];
    const float* fc_b  = (const float*)d_in[14];

    float *pre, *h, *part;
    __nv_bfloat16 *Whi, *Wlo;
    cudaGetSymbolAddress((void**)&pre,  g_pre);
    cudaGetSymbolAddress((void**)&h,    g_h);
    cudaGetSymbolAddress((void**)&part, g_part);
    cudaGetSymbolAddress((void**)&Whi,  g_Whi);
    cudaGetSymbolAddress((void**)&Wlo,  g_Wlo);

    cudaFuncSetAttribute(rnn_scan, cudaFuncAttributeMaxDynamicSharedMemorySize, SCAN_SMEM);
    cudaFuncSetAttribute(gemm0_mma, cudaFuncAttributeMaxDynamicSharedMemorySize, GEMM_SMEM);
    cudaFuncSetAttribute(gemm_abt_bias, cudaFuncAttributeMaxDynamicSharedMemorySize, SG_SMEM);

    // Layer 0: single W split-convert, HMMA GEMM (K-split), reduce, scan
    cvt_split4<<<(H * (KPAD / 4) + 255) / 256, 256>>>(W_ih0, Whi, Wlo, H, DIN);
    gemm0_mma<<<dim3(KSPLIT, M_TOT / 128), 512, GEMM_SMEM>>>(x, Whi, Wlo, part);
    reduce_bias<<<(M_TOT * H + 255) / 256, 256>>>(part, b_ih0, b_hh0, pre);
    rnn_scan<<<B, SCAN_THREADS, SCAN_SMEM>>>(pre, W_hh0, h, fc_w, fc_b, (float*)d_out, 0);

    dim3 gg((H + 63) / 64, M_TOT / 64);   // (4, 32)

    // Layer 1
    gemm_abt_bias<<<gg, 256, SG_SMEM>>>(h, W_ih1, b_ih1, b_hh1, pre);
    rnn_scan<<<B, SCAN_THREADS, SCAN_SMEM>>>(pre, W_hh1, h, fc_w, fc_b, (float*)d_out, 0);

    // Layer 2 (scan fuses the final FC)
    gemm_abt_bias<<<gg, 256, SG_SMEM>>>(h, W_ih2, b_ih2, b_hh2, pre);
    rnn_scan<<<B, SCAN_THREADS, SCAN_SMEM>>>(pre, W_hh2, h, fc_w, fc_b, (float*)d_out, 1);
}